// round 10
// baseline (speedup 1.0000x reference)
#include <cuda_runtime.h>

// entmax-1.5 over rows. zbuf = (mask? s : -1e4)*0.5 (unshifted) in shared.
// tau = root of sum max((z-rmax)-tau,0)^2 = 1, bracketed in [-1,0];
// p = max(z-(rmax+tau),0)^2.
//
// R10 structure: ONE barrier per row.
//  - compact with the WARP-local threshold (wmax-1): superset of the true
//    active set; extra elements contribute 0 in the bisection and are
//    excluded by the closed form's support test (v > lo). This lets the
//    compaction fuse into the load phase (no global-max barrier needed).
//  - after the single __syncthreads, EVERY warp redundantly solves tau from
//    sh_max/abuf (bitwise-identical), then streams its own store slice
//    immediately — no idle warps, no post-solve barrier, warps desync.

constexpr int COLS    = 4096;
constexpr int THREADS = 256;
constexpr int PER     = COLS / THREADS;  // 16
constexpr int VEC     = PER / 4;         // 4
constexpr int NWARP   = THREADS / 32;    // 8
constexpr int NB      = 10;              // bisection iterations
constexpr int CAP     = 256;             // register fast path (8/lane)
constexpr int ACAP    = 1024;

__device__ __forceinline__ float warp_sum(float v) {
#pragma unroll
    for (int off = 16; off > 0; off >>= 1)
        v += __shfl_xor_sync(0xffffffffu, v, off);
    return v;
}

__global__ __launch_bounds__(THREADS, 8) void entmax15_kernel(
    const float* __restrict__ scores,
    const int* __restrict__ mask,
    float* __restrict__ out)
{
    __shared__ float zbuf[COLS];     // full row of z (unshifted)
    __shared__ float abuf[ACAP];     // warp-threshold compacted candidates (raw z)
    __shared__ float sh_max[NWARP];
    __shared__ int   cnt;

    const size_t row = blockIdx.x;
    const float* s = scores + row * COLS;
    const int*   m = mask   + row * COLS;
    float* o = out + row * COLS;

    const int t    = threadIdx.x;
    const int wid  = t >> 5;
    const int lane = t & 31;

    if (t == 0) cnt = 0;   // visible by the single barrier below? NO — must be
                           // ordered before any atomicAdd. Use syncwarp-free
                           // scheme: init via warp 0 lane 0 BEFORE loads issue
                           // and rely on... (see note) — instead init per-row
                           // safely: every CTA handles exactly one row, cnt is
                           // written once here; atomicAdds happen after each
                           // warp's own loads complete, and warp 0 lane 0 wrote
                           // cnt before issuing its loads. Cross-warp ordering:
                           // other warps could atomicAdd before warp 0's store
                           // lands. Guard with a cheap syncthreads-free fence:
    __syncthreads();       // cheap: at kernel start, no work yet to serialize.

    // ---- Load, mask, *0.5 -> shared; track warp-local max ----
    float z[PER];
    float lmax = -3.402823e38f;
#pragma unroll
    for (int c = 0; c < VEC; ++c) {
        const int idx = c * (THREADS * 4) + t * 4;
        float4 v  = __ldcs(reinterpret_cast<const float4*>(s + idx));
        int4   mm = __ldcs(reinterpret_cast<const int4*>(m + idx));
        float z0 = (mm.x ? v.x : -1.0e4f) * 0.5f;
        float z1 = (mm.y ? v.y : -1.0e4f) * 0.5f;
        float z2 = (mm.z ? v.z : -1.0e4f) * 0.5f;
        float z3 = (mm.w ? v.w : -1.0e4f) * 0.5f;
        z[c*4+0] = z0; z[c*4+1] = z1; z[c*4+2] = z2; z[c*4+3] = z3;
        float4 zz; zz.x = z0; zz.y = z1; zz.z = z2; zz.w = z3;
        *reinterpret_cast<float4*>(zbuf + idx) = zz;
        lmax = fmaxf(lmax, fmaxf(fmaxf(z0, z1), fmaxf(z2, z3)));
    }

    // ---- Warp max ----
#pragma unroll
    for (int off = 16; off > 0; off >>= 1)
        lmax = fmaxf(lmax, __shfl_xor_sync(0xffffffffu, lmax, off));
    if (lane == 0) sh_max[wid] = lmax;   // lmax = this warp's max (all lanes)

    // ---- Warp-threshold compaction (superset of true actives) ----
    // wthr = wmax - 1 <= rmax - 1, so every true active in this warp's slice
    // passes. The -2000 floor rejects masked fill (-5000) when a warp's slice
    // is entirely masked (wmax = -5000 would otherwise admit everything).
    const float wthr = fmaxf(lmax - 1.0f, -2000.0f);
#pragma unroll
    for (int i = 0; i < PER; ++i) {
        if (z[i] > wthr) {
            int p = atomicAdd(&cnt, 1);        // warp-aggregated
            if (p < ACAP) abuf[p] = z[i];      // raw z (unshifted)
        }
    }

    // ---- THE barrier: zbuf, abuf, sh_max, cnt all visible after this ----
    __syncthreads();

    // ---- Every warp redundantly solves tau ----
    float rmax = sh_max[0];
#pragma unroll
    for (int i = 1; i < NWARP; ++i) rmax = fmaxf(rmax, sh_max[i]);

    const int n = cnt;
    float lo = -1.0f, hi = 0.0f;
    float tau;

    if (n <= CAP) {
        // fast path: 8 candidates per lane in registers (shifted)
        float v[8];
#pragma unroll
        for (int j = 0; j < 8; ++j) {
            int i = lane + 32 * j;
            v[j] = (i < n) ? (abuf[i] - rmax) : -2.0f;   // sentinel
        }
#pragma unroll 1
        for (int it = 0; it < NB; ++it) {
            const float tm = 0.5f * (lo + hi);
            float acc = 0.0f;
#pragma unroll
            for (int j = 0; j < 8; ++j) {
                float d = fmaxf(v[j] - tm, 0.0f);
                acc = fmaf(d, d, acc);
            }
            if (warp_sum(acc) >= 1.0f) lo = tm; else hi = tm;
        }
        float k = 0.0f, S1 = 0.0f, S2 = 0.0f;
#pragma unroll
        for (int j = 0; j < 8; ++j)
            if (v[j] > lo) { k += 1.0f; S1 += v[j]; S2 = fmaf(v[j], v[j], S2); }
        k = warp_sum(k); S1 = warp_sum(S1); S2 = warp_sum(S2);
        float disc = fmaxf(fmaf(S1, S1, -k * (S2 - 1.0f)), 0.0f);
        tau = (S1 - sqrtf(disc)) / k;
    } else if (n <= ACAP) {
#pragma unroll 1
        for (int it = 0; it < NB; ++it) {
            const float tm = 0.5f * (lo + hi);
            float acc = 0.0f;
            for (int i = lane; i < n; i += 32) {
                float d = fmaxf((abuf[i] - rmax) - tm, 0.0f);
                acc = fmaf(d, d, acc);
            }
            if (warp_sum(acc) >= 1.0f) lo = tm; else hi = tm;
        }
        float k = 0.0f, S1 = 0.0f, S2 = 0.0f;
        for (int i = lane; i < n; i += 32) {
            float v = abuf[i] - rmax;
            if (v > lo) { k += 1.0f; S1 += v; S2 = fmaf(v, v, S2); }
        }
        k = warp_sum(k); S1 = warp_sum(S1); S2 = warp_sum(S2);
        float disc = fmaxf(fmaf(S1, S1, -k * (S2 - 1.0f)), 0.0f);
        tau = (S1 - sqrtf(disc)) / k;
    } else {
        // pathological overflow: scan the full row in shared
#pragma unroll 1
        for (int it = 0; it < NB; ++it) {
            const float tm = 0.5f * (lo + hi);
            float acc = 0.0f;
            for (int i = lane; i < COLS; i += 32) {
                float d = fmaxf((zbuf[i] - rmax) - tm, 0.0f);
                acc = fmaf(d, d, acc);
            }
            if (warp_sum(acc) >= 1.0f) lo = tm; else hi = tm;
        }
        float k = 0.0f, S1 = 0.0f, S2 = 0.0f;
        for (int i = lane; i < COLS; i += 32) {
            float v = zbuf[i] - rmax;
            if (v > lo) { k += 1.0f; S1 += v; S2 = fmaf(v, v, S2); }
        }
        k = warp_sum(k); S1 = warp_sum(S1); S2 = warp_sum(S2);
        float disc = fmaxf(fmaf(S1, S1, -k * (S2 - 1.0f)), 0.0f);
        tau = (S1 - sqrtf(disc)) / k;
    }

    const float taup = tau + rmax;   // p = max(z - taup, 0)^2

    // ---- Store immediately (no barrier; z still live in this warp's regs) ----
#pragma unroll
    for (int c = 0; c < VEC; ++c) {
        const int idx = c * (THREADS * 4) + t * 4;
        float d0 = fmaxf(z[c*4+0] - taup, 0.0f);
        float d1 = fmaxf(z[c*4+1] - taup, 0.0f);
        float d2 = fmaxf(z[c*4+2] - taup, 0.0f);
        float d3 = fmaxf(z[c*4+3] - taup, 0.0f);
        float4 p;
        p.x = d0*d0; p.y = d1*d1; p.z = d2*d2; p.w = d3*d3;
        __stcs(reinterpret_cast<float4*>(o + idx), p);
    }
}

extern "C" void kernel_launch(void* const* d_in, const int* in_sizes, int n_in,
                              void* d_out, int out_size) {
    const float* scores = (const float*)d_in[0];
    const int*   mask   = (const int*)d_in[1];
    float* out = (float*)d_out;
    const int rows = in_sizes[0] / COLS;
    entmax15_kernel<<<rows, THREADS>>>(scores, mask, out);
}

// round 11
// speedup vs baseline: 1.6677x; 1.6677x over previous
#include <cuda_runtime.h>

// entmax-1.5 over rows. z = (mask? s : -1e4)*0.5 (unshifted) in shared;
// active iff z > rmax-1; tau = root of sum max((z-rmax)-tau,0)^2 = 1 in [-1,0];
// p = max(z-(rmax+tau),0)^2. ~140/4096 elements active; solver warp runs 10
// bisections + exact fixed-support closed form
//   tau = (S1 - sqrt(S1^2 - k(S2-1)))/k over support {v > lo}.
//
// R11: 512-thread CTA processes TWO rows (threads 0-255 row A, 256-511 row B).
// Barriers amortized 2x; the two serial solves run concurrently in warp 0
// (SMSP0) and warp 9 (SMSP1). 4 CTAs/SM -> 8 rows in flight, 64/64 warps.

constexpr int COLS    = 4096;
constexpr int THREADS = 512;
constexpr int HALF    = 256;
constexpr int PER     = COLS / HALF;     // 16
constexpr int VEC     = PER / 4;         // 4
constexpr int NWH     = HALF / 32;       // 8 warps per half
constexpr int NB      = 10;
constexpr int CAP     = 128;             // register fast path (4/lane)
constexpr int ACAP    = 512;

__device__ __forceinline__ float warp_sum(float v) {
#pragma unroll
    for (int off = 16; off > 0; off >>= 1)
        v += __shfl_xor_sync(0xffffffffu, v, off);
    return v;
}

__global__ __launch_bounds__(THREADS, 4) void entmax15_kernel(
    const float* __restrict__ scores,
    const int* __restrict__ mask,
    float* __restrict__ out,
    int rows)
{
    __shared__ float zbuf[2 * COLS];     // two rows of z (unshifted)
    __shared__ float abuf[2 * ACAP];     // compacted actives per row (v = z - rmax)
    __shared__ float sh_max[2][NWH];
    __shared__ float sh_taup[2];
    __shared__ int   cnt[2];

    const int t    = threadIdx.x;
    const int half = t >> 8;             // 0 or 1
    const int t2   = t & (HALF - 1);
    const int wh   = t2 >> 5;            // warp index within half
    const int lane = t & 31;
    const int wgl  = t >> 5;             // global warp id 0..15

    const size_t row = (size_t)blockIdx.x * 2 + half;
    const bool   act = row < (size_t)rows;

    const float* s = scores + row * COLS;
    const int*   m = mask   + row * COLS;
    float*       o = out    + row * COLS;
    float*       zrow = zbuf + half * COLS;
    float*       arow = abuf + half * ACAP;

    // ---- Load, mask, *0.5 -> shared; warp-local max ----
    float lmax = -3.402823e38f;
    if (act) {
#pragma unroll
        for (int c = 0; c < VEC; ++c) {
            const int idx = c * (HALF * 4) + t2 * 4;
            float4 v  = __ldcs(reinterpret_cast<const float4*>(s + idx));
            int4   mm = __ldcs(reinterpret_cast<const int4*>(m + idx));
            float4 zz;
            zz.x = (mm.x ? v.x : -1.0e4f) * 0.5f;
            zz.y = (mm.y ? v.y : -1.0e4f) * 0.5f;
            zz.z = (mm.z ? v.z : -1.0e4f) * 0.5f;
            zz.w = (mm.w ? v.w : -1.0e4f) * 0.5f;
            *reinterpret_cast<float4*>(zrow + idx) = zz;
            lmax = fmaxf(lmax, fmaxf(fmaxf(zz.x, zz.y), fmaxf(zz.z, zz.w)));
        }
    }

    // ---- Per-half block max ----
#pragma unroll
    for (int off = 16; off > 0; off >>= 1)
        lmax = fmaxf(lmax, __shfl_xor_sync(0xffffffffu, lmax, off));
    if (lane == 0) sh_max[half][wh] = lmax;
    if (t2 == 0) cnt[half] = 0;
    __syncthreads();
    float rmax = sh_max[half][0];
#pragma unroll
    for (int i = 1; i < NWH; ++i) rmax = fmaxf(rmax, sh_max[half][i]);
    const float thr = rmax - 1.0f;       // active iff z > thr

    // ---- Compact actives from shared (store v = z - rmax) ----
    if (act) {
#pragma unroll
        for (int c = 0; c < VEC; ++c) {
            const int idx = c * (HALF * 4) + t2 * 4;
            float4 zz = *reinterpret_cast<const float4*>(zrow + idx);
#pragma unroll
            for (int j = 0; j < 4; ++j) {
                float zv = (&zz.x)[j];
                if (zv > thr) {
                    int p = atomicAdd(&cnt[half], 1);     // warp-aggregated
                    if (p < ACAP) arow[p] = zv - rmax;
                }
            }
        }
    }
    __syncthreads();

    // ---- Solver warps: warp 0 (row A, SMSP0) and warp 9 (row B, SMSP1) ----
    if (wgl == 0 || wgl == 9) {
        const int sh = (wgl == 0) ? 0 : 1;
        const float* ab = abuf + sh * ACAP;
        const float* zr = zbuf + sh * COLS;
        float rmx = sh_max[sh][0];
#pragma unroll
        for (int i = 1; i < NWH; ++i) rmx = fmaxf(rmx, sh_max[sh][i]);

        const int n = cnt[sh];
        float lo = -1.0f, hi = 0.0f;
        float tau = 0.0f;

        if (n >= 1 && n <= CAP) {
            float v[4];
#pragma unroll
            for (int j = 0; j < 4; ++j) {
                int i = lane + 32 * j;
                v[j] = (i < n) ? ab[i] : -2.0f;          // sentinel
            }
#pragma unroll 1
            for (int it = 0; it < NB; ++it) {
                const float tm = 0.5f * (lo + hi);
                float acc = 0.0f;
#pragma unroll
                for (int j = 0; j < 4; ++j) {
                    float d = fmaxf(v[j] - tm, 0.0f);
                    acc = fmaf(d, d, acc);
                }
                if (warp_sum(acc) >= 1.0f) lo = tm; else hi = tm;
            }
            float k = 0.0f, S1 = 0.0f, S2 = 0.0f;
#pragma unroll
            for (int j = 0; j < 4; ++j)
                if (v[j] > lo) { k += 1.0f; S1 += v[j]; S2 = fmaf(v[j], v[j], S2); }
            k = warp_sum(k); S1 = warp_sum(S1); S2 = warp_sum(S2);
            float disc = fmaxf(fmaf(S1, S1, -k * (S2 - 1.0f)), 0.0f);
            tau = (S1 - sqrtf(disc)) / k;
        } else if (n >= 1 && n <= ACAP) {
#pragma unroll 1
            for (int it = 0; it < NB; ++it) {
                const float tm = 0.5f * (lo + hi);
                float acc = 0.0f;
                for (int i = lane; i < n; i += 32) {
                    float d = fmaxf(ab[i] - tm, 0.0f);
                    acc = fmaf(d, d, acc);
                }
                if (warp_sum(acc) >= 1.0f) lo = tm; else hi = tm;
            }
            float k = 0.0f, S1 = 0.0f, S2 = 0.0f;
            for (int i = lane; i < n; i += 32) {
                float v = ab[i];
                if (v > lo) { k += 1.0f; S1 += v; S2 = fmaf(v, v, S2); }
            }
            k = warp_sum(k); S1 = warp_sum(S1); S2 = warp_sum(S2);
            float disc = fmaxf(fmaf(S1, S1, -k * (S2 - 1.0f)), 0.0f);
            tau = (S1 - sqrtf(disc)) / k;
        } else if (n > ACAP) {
            // pathological overflow: scan the full row in shared
#pragma unroll 1
            for (int it = 0; it < NB; ++it) {
                const float tm = 0.5f * (lo + hi);
                float acc = 0.0f;
                for (int i = lane; i < COLS; i += 32) {
                    float d = fmaxf((zr[i] - rmx) - tm, 0.0f);
                    acc = fmaf(d, d, acc);
                }
                if (warp_sum(acc) >= 1.0f) lo = tm; else hi = tm;
            }
            float k = 0.0f, S1 = 0.0f, S2 = 0.0f;
            for (int i = lane; i < COLS; i += 32) {
                float v = zr[i] - rmx;
                if (v > lo) { k += 1.0f; S1 += v; S2 = fmaf(v, v, S2); }
            }
            k = warp_sum(k); S1 = warp_sum(S1); S2 = warp_sum(S2);
            float disc = fmaxf(fmaf(S1, S1, -k * (S2 - 1.0f)), 0.0f);
            tau = (S1 - sqrtf(disc)) / k;
        }
        // n == 0 only for an inactive (out-of-range) row: tau unused.
        if (lane == 0) sh_taup[sh] = tau + rmx;
    }
    __syncthreads();
    const float taup = sh_taup[half];    // p = max(z - taup, 0)^2

    // ---- Store p from shared ----
    if (act) {
#pragma unroll
        for (int c = 0; c < VEC; ++c) {
            const int idx = c * (HALF * 4) + t2 * 4;
            float4 zz = *reinterpret_cast<const float4*>(zrow + idx);
            float d0 = fmaxf(zz.x - taup, 0.0f);
            float d1 = fmaxf(zz.y - taup, 0.0f);
            float d2 = fmaxf(zz.z - taup, 0.0f);
            float d3 = fmaxf(zz.w - taup, 0.0f);
            float4 p;
            p.x = d0*d0; p.y = d1*d1; p.z = d2*d2; p.w = d3*d3;
            __stcs(reinterpret_cast<float4*>(o + idx), p);
        }
    }
}

extern "C" void kernel_launch(void* const* d_in, const int* in_sizes, int n_in,
                              void* d_out, int out_size) {
    const float* scores = (const float*)d_in[0];
    const int*   mask   = (const int*)d_in[1];
    float* out = (float*)d_out;
    const int rows = in_sizes[0] / COLS;
    const int grid = (rows + 1) / 2;
    entmax15_kernel<<<grid, THREADS>>>(scores, mask, out, rows);
}